// round 14
// baseline (speedup 1.0000x reference)
#include <cuda_runtime.h>
#include <cuda_bf16.h>
#include <cstdint>

// Problem constants: N=4096, L_V=64, H=512, D=256
constexpr int NB   = 4096;
constexpr int LV   = 64;
constexpr int HD   = 512;
constexpr int DD   = 256;
constexpr int K1   = 3 * DD;   // 768
constexpr int KTOT = K1 + HD;  // 1280

// GEMM tiling: CTA tile 128x128, K stepped by 16 (one m16n8k16 per step)
constexpr int BM = 128, BN = 128, BKS = 16;
constexpr int NIT = KTOT / BKS;                    // 80
constexpr int GEMM_CTAS  = (NB / BM) * (HD / BN);  // 128
constexpr int TOTAL_CTAS = 304;                    // 2 per SM on 152 SMs (all wave-1)

// Copy pool
constexpr int ROWS_TOTAL = NB * LV;                // 262144 rows of 512 floats
constexpr int NUM_GRABS  = ROWS_TOTAL / 32;        // 8192

// In-kernel conversion geometry
constexpr int XSLICE_ROWS   = 32;                  // rows per GEMM CTA
constexpr int XSLICE_CHUNKS = XSLICE_ROWS * (KTOT / 4);  // 10240 float4 chunks
constexpr int WKT = 64, WNT = 32;                  // W transpose tile

__device__ int g_copy_ctr;                         // zero-init; self-reset
__device__ int g_done;                             // CTA completion counter
__device__ int g_xdone[NB / BM];                   // per m-block X-plane arrivals
__device__ int g_wdone[HD / BN];                   // per n-block W-plane arrivals
__device__ __align__(16) __nv_bfloat16 g_xhi[NB * KTOT];  // X hi plane (10MB)
__device__ __align__(16) __nv_bfloat16 g_xlo[NB * KTOT];  // X lo plane
__device__ __align__(16) __nv_bfloat16 g_whi[HD * KTOT];  // W^T hi (k-major)
__device__ __align__(16) __nv_bfloat16 g_wlo[HD * KTOT];  // W^T lo

// ---------------- PTX helpers ----------------
__device__ __forceinline__ uint32_t s2u(const void* p) {
    uint32_t a;
    asm("{ .reg .u64 t; cvta.to.shared.u64 t, %1; cvt.u32.u64 %0, t; }"
        : "=r"(a) : "l"(p));
    return a;
}
__device__ __forceinline__ void cp16(uint32_t dst, const void* src) {
    asm volatile("cp.async.cg.shared.global [%0], [%1], 16;" :: "r"(dst), "l"(src));
}
__device__ __forceinline__ void cp_commit() {
    asm volatile("cp.async.commit_group;");
}
template <int N>
__device__ __forceinline__ void cp_wait() {
    asm volatile("cp.async.wait_group %0;" :: "n"(N));
}
__device__ __forceinline__ void ldsm4(uint32_t* r, uint32_t addr) {
    asm volatile("ldmatrix.sync.aligned.m8n8.x4.shared.b16 {%0,%1,%2,%3}, [%4];"
                 : "=r"(r[0]), "=r"(r[1]), "=r"(r[2]), "=r"(r[3]) : "r"(addr));
}
__device__ __forceinline__ void mma16816(float* d, const uint32_t* a,
                                         const uint32_t* b) {
    asm volatile(
        "mma.sync.aligned.m16n8k16.row.col.f32.bf16.bf16.f32 "
        "{%0,%1,%2,%3}, {%4,%5,%6,%7}, {%8,%9}, {%0,%1,%2,%3};"
        : "+f"(d[0]), "+f"(d[1]), "+f"(d[2]), "+f"(d[3])
        : "r"(a[0]), "r"(a[1]), "r"(a[2]), "r"(a[3]), "r"(b[0]), "r"(b[1]));
}
__device__ __forceinline__ float4 ldcs(const float4* p) {
    float4 v;
    asm volatile("ld.global.cs.v4.f32 {%0,%1,%2,%3}, [%4];"
                 : "=f"(v.x), "=f"(v.y), "=f"(v.z), "=f"(v.w) : "l"(p));
    return v;
}
__device__ __forceinline__ void stcs(float4* p, float4 v) {
    asm volatile("st.global.cs.v4.f32 [%0], {%1,%2,%3,%4};"
                 :: "l"(p), "f"(v.x), "f"(v.y), "f"(v.z), "f"(v.w) : "memory");
}
__device__ __forceinline__ uint32_t pack_hi2(float a, float b,
                                             float& ra, float& rb) {
    __nv_bfloat16 h0 = __float2bfloat16_rn(a);
    __nv_bfloat16 h1 = __float2bfloat16_rn(b);
    ra = a - __bfloat162float(h0);
    rb = b - __bfloat162float(h1);
    return ((uint32_t)*(uint16_t*)&h1 << 16) | *(uint16_t*)&h0;
}
__device__ __forceinline__ uint32_t pack_bf2(float a, float b) {
    __nv_bfloat162 t = __floats2bfloat162_rn(a, b);
    return *reinterpret_cast<uint32_t*>(&t);
}

// --------------------------------------------------------------------------
// Copy role: work-stealing passthrough. Skips both load and store of the row
// each batch's GEMM scatters. Warp grabs 32 rows; up to 16 LDG.128 in flight.
// --------------------------------------------------------------------------
__device__ __forceinline__ void copy_role(const float4* __restrict__ src,
                                          float4* __restrict__ dst,
                                          const int* __restrict__ veh_idx,
                                          int lane)
{
    for (;;) {
        int c;
        if (lane == 0) c = atomicAdd(&g_copy_ctr, 1);
        c = __shfl_sync(0xffffffffu, c, 0);
        if (c >= NUM_GRABS) return;

        const int r0   = c * 32;            // same n for the whole grab
        const int n    = r0 >> 6;
        const int skip = veh_idx[n] & (LV - 1);
        const int l0   = r0 & 63;

        for (int g = 0; g < 8; g++) {
            float4 v[16];
            size_t base = (size_t)(r0 + g * 4) * (HD / 4) + lane;
            #pragma unroll
            for (int rr = 0; rr < 4; rr++) {
                if (l0 + g * 4 + rr == skip) continue;   // dead row: no read
                #pragma unroll
                for (int q = 0; q < 4; q++)
                    v[rr * 4 + q] = ldcs(src + base + rr * 128 + q * 32);
            }
            #pragma unroll
            for (int rr = 0; rr < 4; rr++) {
                if (l0 + g * 4 + rr == skip) continue;   // GEMM writes this row
                #pragma unroll
                for (int q = 0; q < 4; q++)
                    stcs(dst + base + rr * 128 + q * 32, v[rr * 4 + q]);
            }
        }
    }
}

// --------------------------------------------------------------------------
// Single fused kernel (no prep launch).
//  bids [0,128): (1) convert own 32-row X slice to bf16 hi/lo planes
//                (2) bids 0-3 also transpose+split W for their n-block
//                (3) flag release / acquire across the 304 co-resident CTAs
//                (4) R11-proven mma.sync GEMM, epilogue scatters to out
//  bids [128,304): copy pool from t=0.
//  Last CTA out resets all counters for the next graph replay.
// --------------------------------------------------------------------------
__global__ __launch_bounds__(256, 2)
void fused_kernel(const float* __restrict__ memory,
                  const int*   __restrict__ veh_idx,
                  const float* __restrict__ veh_repr,
                  const float* __restrict__ cust_repr,
                  const float* __restrict__ edge_emb,
                  const float* __restrict__ W_in,
                  const float* __restrict__ W_h,
                  const float* __restrict__ b_in,
                  const float* __restrict__ b_h,
                  float* __restrict__ out)
{
    // GEMM: 3 stages x 16KB (xhi | xlo | whi | wlo). Also reused as the W
    // transpose tile before the pipeline starts.
    __shared__ __align__(128) char raw[49152];

    const int tid  = threadIdx.x;
    const int bid  = blockIdx.x;
    const int lane = tid & 31;

    if (bid < GEMM_CTAS) {
        const int mb = bid >> 2;            // m-block 0..31
        const int q  = bid & 3;             // quarter / n-block 0..3
        const int block_m = mb * BM;
        const int block_n = q * BN;

        // ================= (1) X slice conversion: 32 rows =================
        {
            const int slice_m = block_m + q * XSLICE_ROWS;
            for (int g = 0; g < XSLICE_CHUNKS / (256 * 4); g++) {   // 10 groups
                float4 v[4];
                int    eidx[4];
                #pragma unroll
                for (int u = 0; u < 4; u++) {
                    const int c = (g * 4 + u) * 256 + tid;   // chunk in slice
                    const int m = slice_m + c / (KTOT / 4);
                    const int k = (c % (KTOT / 4)) * 4;
                    eidx[u] = m * KTOT + k;
                    const float* src;
                    if (k < DD)          src = veh_repr  + (size_t)m * DD + k;
                    else if (k < 2 * DD) src = cust_repr + (size_t)m * DD + (k - DD);
                    else if (k < K1)     src = edge_emb  + (size_t)m * DD + (k - 2 * DD);
                    else {
                        const int idx = veh_idx[m] & (LV - 1);
                        src = memory + ((size_t)m * LV + idx) * HD + (k - K1);
                    }
                    v[u] = *(const float4*)src;              // 4 loads batched
                }
                #pragma unroll
                for (int u = 0; u < 4; u++) {
                    float r0, r1, r2, r3;
                    uint2 ph, pl;
                    ph.x = pack_hi2(v[u].x, v[u].y, r0, r1);
                    ph.y = pack_hi2(v[u].z, v[u].w, r2, r3);
                    pl.x = pack_bf2(r0, r1);
                    pl.y = pack_bf2(r2, r3);
                    *(uint2*)&g_xhi[eidx[u]] = ph;
                    *(uint2*)&g_xlo[eidx[u]] = pl;
                }
            }
        }

        // ============ (2) W conversion for n-block q (bids 0-3) =============
        if (bid < 4) {
            float (*tile)[WNT + 1] = (float (*)[WNT + 1])raw;   // 64 x 33
            for (int t = 0; t < (KTOT / WKT) * (BN / WNT); t++) {   // 80 tiles
                const int k0 = (t % (KTOT / WKT)) * WKT;
                const int n0 = block_n + (t / (KTOT / WKT)) * WNT;
                const float* W = (k0 < K1) ? (W_in + (size_t)k0 * HD)
                                           : (W_h + (size_t)(k0 - K1) * HD);
                #pragma unroll
                for (int i = 0; i < 8; i++) {
                    const int e2 = tid + i * 256;
                    tile[e2 >> 5][e2 & 31] = W[(size_t)(e2 >> 5) * HD + n0 + (e2 & 31)];
                }
                __syncthreads();
                #pragma unroll
                for (int i = 0; i < 4; i++) {
                    const int p  = tid + i * 256;
                    const int n  = p >> 5;
                    const int kk = (p & 31) * 2;
                    float r0, r1;
                    const uint32_t hi = pack_hi2(tile[kk][n], tile[kk + 1][n], r0, r1);
                    const uint32_t lo = pack_bf2(r0, r1);
                    const size_t off = (size_t)(n0 + n) * KTOT + k0 + kk;
                    *(uint32_t*)&g_whi[off] = hi;
                    *(uint32_t*)&g_wlo[off] = lo;
                }
                __syncthreads();
            }
        }

        // ================= (3) release / acquire flags =====================
        __syncthreads();
        if (tid == 0) {
            __threadfence();                     // release plane writes
            atomicAdd(&g_xdone[mb], 1);
            if (bid < 4) atomicAdd(&g_wdone[q], 1);
            while (atomicAdd(&g_xdone[mb], 0) < 4) __nanosleep(200);
            while (atomicAdd(&g_wdone[q], 0) < 1)  __nanosleep(200);
        }
        __syncthreads();                         // planes ready CTA-wide
        // cp.async.cg below bypasses L1 -> reads L2-coherent plane data.

        // ================= (4) GEMM (R11-proven structure) =================
        const int w  = tid >> 5;
        const int wm = w >> 1;          // 0..3 -> rows wm*32
        const int wn = w & 1;           // 0..1 -> cols wn*64
        const uint32_t sbase = s2u(raw);

        const int row  = tid >> 1;
        const int half = tid & 1;
        const uint32_t dxy = (uint32_t)(row * 32 + half * 16);
        const size_t gx = (size_t)(block_m + row) * KTOT + half * 8;
        const size_t gw = (size_t)(block_n + row) * KTOT + half * 8;

        auto issue = [&](int it, int buf) {
            const int k0 = it * BKS;
            const uint32_t sb = sbase + (uint32_t)buf * 16384;
            cp16(sb + dxy,          g_xhi + gx + k0);
            cp16(sb + 4096 + dxy,   g_xlo + gx + k0);
            cp16(sb + 8192 + dxy,   g_whi + gw + k0);
            cp16(sb + 12288 + dxy,  g_wlo + gw + k0);
            cp_commit();
        };

        uint32_t aoff[2];
        #pragma unroll
        for (int i = 0; i < 2; i++) {
            const int r = wm * 32 + i * 16 + (lane & 7) + ((lane >> 3) & 1) * 8;
            aoff[i] = (uint32_t)(r * 32 + ((lane >> 4) & 1) * 16);
        }
        uint32_t boff[4];
        #pragma unroll
        for (int p = 0; p < 4; p++) {
            const int r = wn * 64 + p * 16 + (lane & 7) + ((lane >> 4) & 1) * 8;
            boff[p] = (uint32_t)(r * 32 + ((lane >> 3) & 1) * 16);
        }

        float d[2][8][4];
        #pragma unroll
        for (int i = 0; i < 2; i++)
            #pragma unroll
            for (int j = 0; j < 8; j++)
                #pragma unroll
                for (int qq = 0; qq < 4; qq++) d[i][j][qq] = 0.0f;

        issue(0, 0);
        issue(1, 1);

        int buf = 0, nbuf = 2;
        for (int it = 0; it < NIT; it++) {
            if (it + 2 < NIT) cp_wait<1>(); else cp_wait<0>();
            __syncthreads();
            if (it + 2 < NIT) issue(it + 2, nbuf);

            const uint32_t sb = sbase + (uint32_t)buf * 16384;
            uint32_t ah[2][4], al[2][4], bb[8][2];
            ldsm4(ah[0], sb + aoff[0]);
            ldsm4(ah[1], sb + aoff[1]);
            ldsm4(al[0], sb + 4096 + aoff[0]);
            ldsm4(al[1], sb + 4096 + aoff[1]);
            #pragma unroll
            for (int p = 0; p < 4; p++) {
                uint32_t r[4];
                ldsm4(r, sb + 8192 + boff[p]);      // W hi
                bb[2 * p][0] = r[0]; bb[2 * p][1] = r[1];
                bb[2 * p + 1][0] = r[2]; bb[2 * p + 1][1] = r[3];
            }
            #pragma unroll
            for (int i = 0; i < 2; i++)
                #pragma unroll
                for (int j = 0; j < 8; j++) {
                    mma16816(d[i][j], ah[i], bb[j]);   // hi*hi
                    mma16816(d[i][j], al[i], bb[j]);   // lo*hi
                }
            #pragma unroll
            for (int p = 0; p < 4; p++) {
                uint32_t r[4];
                ldsm4(r, sb + 12288 + boff[p]);     // W lo
                bb[2 * p][0] = r[0]; bb[2 * p][1] = r[1];
                bb[2 * p + 1][0] = r[2]; bb[2 * p + 1][1] = r[3];
            }
            #pragma unroll
            for (int i = 0; i < 2; i++)
                #pragma unroll
                for (int j = 0; j < 8; j++)
                    mma16816(d[i][j], ah[i], bb[j]);   // hi*lo

            buf  = (buf  == 2) ? 0 : buf + 1;
            nbuf = (nbuf == 2) ? 0 : nbuf + 1;
        }

        // epilogue: bias + tanh -> scatter directly to out[n, idx[n], :]
        float2 bias[8];
        #pragma unroll
        for (int j = 0; j < 8; j++) {
            const int col = block_n + wn * 64 + j * 8 + (lane & 3) * 2;
            bias[j].x = b_in[col] + b_h[col];
            bias[j].y = b_in[col + 1] + b_h[col + 1];
        }
        #pragma unroll
        for (int i = 0; i < 2; i++) {
            const int m0 = block_m + wm * 32 + i * 16 + (lane >> 2);
            const int m1 = m0 + 8;
            const size_t base0 = ((size_t)m0 * LV + (veh_idx[m0] & (LV - 1))) * HD;
            const size_t base1 = ((size_t)m1 * LV + (veh_idx[m1] & (LV - 1))) * HD;
            #pragma unroll
            for (int j = 0; j < 8; j++) {
                const int col = block_n + wn * 64 + j * 8 + (lane & 3) * 2;
                float2 v0, v1;
                v0.x = tanhf(d[i][j][0] + bias[j].x);
                v0.y = tanhf(d[i][j][1] + bias[j].y);
                v1.x = tanhf(d[i][j][2] + bias[j].x);
                v1.y = tanhf(d[i][j][3] + bias[j].y);
                *(float2*)&out[base0 + col] = v0;
                *(float2*)&out[base1 + col] = v1;
            }
        }
    }

    // Copy pool (copy-only CTAs arrive here at t=0; GEMM CTAs after epilogue).
    copy_role((const float4*)memory, (float4*)out, veh_idx, lane);

    // Last CTA out resets all counters for the next graph replay.
    __syncthreads();
    if (tid == 0) {
        const int dcount = atomicAdd(&g_done, 1);
        if (dcount == TOTAL_CTAS - 1) {
            g_copy_ctr = 0;
            #pragma unroll
            for (int i = 0; i < NB / BM; i++) g_xdone[i] = 0;
            #pragma unroll
            for (int i = 0; i < HD / BN; i++) g_wdone[i] = 0;
            __threadfence();
            g_done = 0;
        }
    }
}

extern "C" void kernel_launch(void* const* d_in, const int* in_sizes, int n_in,
                              void* d_out, int out_size)
{
    const float* memory    = (const float*)d_in[0];
    const int*   veh_idx   = (const int*)d_in[1];
    const float* veh_repr  = (const float*)d_in[2];
    const float* cust_repr = (const float*)d_in[3];
    const float* edge_emb  = (const float*)d_in[4];
    const float* W_in      = (const float*)d_in[5];
    const float* b_in      = (const float*)d_in[6];
    const float* W_h       = (const float*)d_in[7];
    const float* b_h       = (const float*)d_in[8];
    float*       out       = (float*)d_out;

    fused_kernel<<<TOTAL_CTAS, 256>>>(memory, veh_idx, veh_repr, cust_repr,
                                      edge_emb, W_in, W_h, b_in, b_h, out);
}

// round 15
// speedup vs baseline: 1.5933x; 1.5933x over previous
#include <cuda_runtime.h>
#include <cuda_bf16.h>
#include <cstdint>

// Problem constants: N=4096, L_V=64, H=512, D=256
constexpr int NB   = 4096;
constexpr int LV   = 64;
constexpr int HD   = 512;
constexpr int DD   = 256;
constexpr int K1   = 3 * DD;   // 768
constexpr int KTOT = K1 + HD;  // 1280

// GEMM tiling: CTA tile 128x128, K stepped by 16 (one m16n8k16 per step)
constexpr int BM = 128, BN = 128, BKS = 16;
constexpr int NIT = KTOT / BKS;                    // 80
constexpr int GEMM_CTAS  = (NB / BM) * (HD / BN);  // 128
constexpr int TOTAL_CTAS = 304;                    // 2 per SM on 152 SMs (all wave-1)

// Copy pool
constexpr int ROWS_TOTAL = NB * LV;                // 262144 rows of 512 floats
constexpr int NUM_GRABS  = ROWS_TOTAL / 32;        // 8192

// In-kernel conversion geometry
constexpr int XSLICE_ROWS   = 32;                  // X rows per GEMM CTA
constexpr int XSLICE_CHUNKS = XSLICE_ROWS * (KTOT / 4);  // 10240 float4 chunks
constexpr int WCOLS = 4;                           // W columns per GEMM CTA

__device__ int g_copy_ctr;                         // zero-init; self-reset
__device__ int g_done;                             // CTA completion counter
__device__ int g_xdone[NB / BM];                   // per m-block X arrivals (4)
__device__ int g_wdone[HD / BN];                   // per n-block W arrivals (32)
__device__ __align__(16) __nv_bfloat16 g_xhi[NB * KTOT];  // X hi plane (10MB)
__device__ __align__(16) __nv_bfloat16 g_xlo[NB * KTOT];  // X lo plane
__device__ __align__(16) __nv_bfloat16 g_whi[HD * KTOT];  // W^T hi (k-major)
__device__ __align__(16) __nv_bfloat16 g_wlo[HD * KTOT];  // W^T lo

// ---------------- PTX helpers ----------------
__device__ __forceinline__ uint32_t s2u(const void* p) {
    uint32_t a;
    asm("{ .reg .u64 t; cvta.to.shared.u64 t, %1; cvt.u32.u64 %0, t; }"
        : "=r"(a) : "l"(p));
    return a;
}
__device__ __forceinline__ void cp16(uint32_t dst, const void* src) {
    asm volatile("cp.async.cg.shared.global [%0], [%1], 16;" :: "r"(dst), "l"(src));
}
__device__ __forceinline__ void cp_commit() {
    asm volatile("cp.async.commit_group;");
}
template <int N>
__device__ __forceinline__ void cp_wait() {
    asm volatile("cp.async.wait_group %0;" :: "n"(N));
}
__device__ __forceinline__ void ldsm4(uint32_t* r, uint32_t addr) {
    asm volatile("ldmatrix.sync.aligned.m8n8.x4.shared.b16 {%0,%1,%2,%3}, [%4];"
                 : "=r"(r[0]), "=r"(r[1]), "=r"(r[2]), "=r"(r[3]) : "r"(addr));
}
__device__ __forceinline__ void mma16816(float* d, const uint32_t* a,
                                         const uint32_t* b) {
    asm volatile(
        "mma.sync.aligned.m16n8k16.row.col.f32.bf16.bf16.f32 "
        "{%0,%1,%2,%3}, {%4,%5,%6,%7}, {%8,%9}, {%0,%1,%2,%3};"
        : "+f"(d[0]), "+f"(d[1]), "+f"(d[2]), "+f"(d[3])
        : "r"(a[0]), "r"(a[1]), "r"(a[2]), "r"(a[3]), "r"(b[0]), "r"(b[1]));
}
__device__ __forceinline__ float4 ldcs(const float4* p) {
    float4 v;
    asm volatile("ld.global.cs.v4.f32 {%0,%1,%2,%3}, [%4];"
                 : "=f"(v.x), "=f"(v.y), "=f"(v.z), "=f"(v.w) : "l"(p));
    return v;
}
__device__ __forceinline__ void stcs(float4* p, float4 v) {
    asm volatile("st.global.cs.v4.f32 [%0], {%1,%2,%3,%4};"
                 :: "l"(p), "f"(v.x), "f"(v.y), "f"(v.z), "f"(v.w) : "memory");
}
__device__ __forceinline__ uint32_t pack_hi2(float a, float b,
                                             float& ra, float& rb) {
    __nv_bfloat16 h0 = __float2bfloat16_rn(a);
    __nv_bfloat16 h1 = __float2bfloat16_rn(b);
    ra = a - __bfloat162float(h0);
    rb = b - __bfloat162float(h1);
    return ((uint32_t)*(uint16_t*)&h1 << 16) | *(uint16_t*)&h0;
}
__device__ __forceinline__ uint32_t pack_bf2(float a, float b) {
    __nv_bfloat162 t = __floats2bfloat162_rn(a, b);
    return *reinterpret_cast<uint32_t*>(&t);
}

// --------------------------------------------------------------------------
// Copy role: work-stealing passthrough. Skips both load and store of the row
// each batch's GEMM scatters. Warp grabs 32 rows; up to 16 LDG.128 in flight.
// --------------------------------------------------------------------------
__device__ __forceinline__ void copy_role(const float4* __restrict__ src,
                                          float4* __restrict__ dst,
                                          const int* __restrict__ veh_idx,
                                          int lane)
{
    for (;;) {
        int c;
        if (lane == 0) c = atomicAdd(&g_copy_ctr, 1);
        c = __shfl_sync(0xffffffffu, c, 0);
        if (c >= NUM_GRABS) return;

        const int r0   = c * 32;            // same n for the whole grab
        const int n    = r0 >> 6;
        const int skip = veh_idx[n] & (LV - 1);
        const int l0   = r0 & 63;

        for (int g = 0; g < 8; g++) {
            float4 v[16];
            size_t base = (size_t)(r0 + g * 4) * (HD / 4) + lane;
            #pragma unroll
            for (int rr = 0; rr < 4; rr++) {
                if (l0 + g * 4 + rr == skip) continue;   // dead row: no read
                #pragma unroll
                for (int q = 0; q < 4; q++)
                    v[rr * 4 + q] = ldcs(src + base + rr * 128 + q * 32);
            }
            #pragma unroll
            for (int rr = 0; rr < 4; rr++) {
                if (l0 + g * 4 + rr == skip) continue;   // GEMM writes this row
                #pragma unroll
                for (int q = 0; q < 4; q++)
                    stcs(dst + base + rr * 128 + q * 32, v[rr * 4 + q]);
            }
        }
    }
}

// --------------------------------------------------------------------------
// Single fused kernel (no prep launch).
//  bids [0,128): (1) convert own 32-row X slice to bf16 hi/lo planes
//                (2) convert own 4-column W sliver (distributed 32x per
//                    n-block — fixes R14's serialized-W regression)
//                (3) flag release / acquire across the 304 co-resident CTAs
//                (4) R11-proven mma.sync GEMM, epilogue scatters to out
//  bids [128,304): copy pool from t=0.
//  Last CTA out resets all counters for the next graph replay.
// --------------------------------------------------------------------------
__global__ __launch_bounds__(256, 2)
void fused_kernel(const float* __restrict__ memory,
                  const int*   __restrict__ veh_idx,
                  const float* __restrict__ veh_repr,
                  const float* __restrict__ cust_repr,
                  const float* __restrict__ edge_emb,
                  const float* __restrict__ W_in,
                  const float* __restrict__ W_h,
                  const float* __restrict__ b_in,
                  const float* __restrict__ b_h,
                  float* __restrict__ out)
{
    // GEMM: 3 stages x 16KB (xhi | xlo | whi | wlo). Also reused as the W
    // transpose staging (20KB) before the pipeline starts.
    __shared__ __align__(128) char raw[49152];

    const int tid  = threadIdx.x;
    const int bid  = blockIdx.x;
    const int lane = tid & 31;

    if (bid < GEMM_CTAS) {
        const int mb = bid >> 2;            // m-block 0..31
        const int q  = bid & 3;             // n-block 0..3
        const int block_m = mb * BM;
        const int block_n = q * BN;

        // ================= (1) X slice conversion: 32 rows =================
        {
            const int slice_m = block_m + q * XSLICE_ROWS;
            for (int g = 0; g < XSLICE_CHUNKS / (256 * 4); g++) {   // 10 groups
                float4 v[4];
                int    eidx[4];
                #pragma unroll
                for (int u = 0; u < 4; u++) {
                    const int c = (g * 4 + u) * 256 + tid;   // chunk in slice
                    const int m = slice_m + c / (KTOT / 4);
                    const int k = (c % (KTOT / 4)) * 4;
                    eidx[u] = m * KTOT + k;
                    const float* src;
                    if (k < DD)          src = veh_repr  + (size_t)m * DD + k;
                    else if (k < 2 * DD) src = cust_repr + (size_t)m * DD + (k - DD);
                    else if (k < K1)     src = edge_emb  + (size_t)m * DD + (k - 2 * DD);
                    else {
                        const int idx = veh_idx[m] & (LV - 1);
                        src = memory + ((size_t)m * LV + idx) * HD + (k - K1);
                    }
                    v[u] = *(const float4*)src;              // 4 loads batched
                }
                #pragma unroll
                for (int u = 0; u < 4; u++) {
                    float r0, r1, r2, r3;
                    uint2 ph, pl;
                    ph.x = pack_hi2(v[u].x, v[u].y, r0, r1);
                    ph.y = pack_hi2(v[u].z, v[u].w, r2, r3);
                    pl.x = pack_bf2(r0, r1);
                    pl.y = pack_bf2(r2, r3);
                    *(uint2*)&g_xhi[eidx[u]] = ph;
                    *(uint2*)&g_xlo[eidx[u]] = pl;
                }
            }
        }

        // ===== (2) W sliver: 4 columns x 1280 k (distributed 32x/n-block) ====
        {
            float (*tile)[WCOLS] = (float (*)[WCOLS])raw;    // [1280][4] = 20KB
            const int nw0 = block_n + mb * WCOLS;            // this CTA's 4 cols
            // load: 5 float4 per thread, coalesced along n within each k-row
            #pragma unroll
            for (int i = 0; i < 5; i++) {
                const int k = tid + i * 256;                 // 0..1279
                const float* Wrow = (k < K1) ? (W_in + (size_t)k * HD)
                                             : (W_h + (size_t)(k - K1) * HD);
                *(float4*)tile[k] = *(const float4*)&Wrow[nw0];
            }
            __syncthreads();
            // write: packed k-pairs, coalesced along k
            #pragma unroll
            for (int i = 0; i < 10; i++) {
                const int idx = i * 256 + tid;               // 0..2559
                const int n   = idx / (KTOT / 2);            // 0..3
                const int kk  = (idx % (KTOT / 2)) * 2;      // even k
                float r0, r1;
                const uint32_t hi = pack_hi2(tile[kk][n], tile[kk + 1][n], r0, r1);
                const uint32_t lo = pack_bf2(r0, r1);
                const size_t off = (size_t)(nw0 + n) * KTOT + kk;
                *(uint32_t*)&g_whi[off] = hi;
                *(uint32_t*)&g_wlo[off] = lo;
            }
            __syncthreads();       // raw free for the GEMM pipeline
        }

        // ================= (3) release / acquire flags =====================
        if (tid == 0) {
            __threadfence();                     // release plane writes
            atomicAdd(&g_xdone[mb], 1);
            atomicAdd(&g_wdone[q], 1);
            while (atomicAdd(&g_xdone[mb], 0) < 4)  __nanosleep(200);
            while (atomicAdd(&g_wdone[q], 0) < 32)  __nanosleep(200);
        }
        __syncthreads();                         // planes ready CTA-wide
        // cp.async.cg below bypasses L1 -> reads L2-coherent plane data.

        // ================= (4) GEMM (R11-proven structure) =================
        const int w  = tid >> 5;
        const int wm = w >> 1;          // 0..3 -> rows wm*32
        const int wn = w & 1;           // 0..1 -> cols wn*64
        const uint32_t sbase = s2u(raw);

        const int row  = tid >> 1;
        const int half = tid & 1;
        const uint32_t dxy = (uint32_t)(row * 32 + half * 16);
        const size_t gx = (size_t)(block_m + row) * KTOT + half * 8;
        const size_t gw = (size_t)(block_n + row) * KTOT + half * 8;

        auto issue = [&](int it, int buf) {
            const int k0 = it * BKS;
            const uint32_t sb = sbase + (uint32_t)buf * 16384;
            cp16(sb + dxy,          g_xhi + gx + k0);
            cp16(sb + 4096 + dxy,   g_xlo + gx + k0);
            cp16(sb + 8192 + dxy,   g_whi + gw + k0);
            cp16(sb + 12288 + dxy,  g_wlo + gw + k0);
            cp_commit();
        };

        uint32_t aoff[2];
        #pragma unroll
        for (int i = 0; i < 2; i++) {
            const int r = wm * 32 + i * 16 + (lane & 7) + ((lane >> 3) & 1) * 8;
            aoff[i] = (uint32_t)(r * 32 + ((lane >> 4) & 1) * 16);
        }
        uint32_t boff[4];
        #pragma unroll
        for (int p = 0; p < 4; p++) {
            const int r = wn * 64 + p * 16 + (lane & 7) + ((lane >> 4) & 1) * 8;
            boff[p] = (uint32_t)(r * 32 + ((lane >> 3) & 1) * 16);
        }

        float d[2][8][4];
        #pragma unroll
        for (int i = 0; i < 2; i++)
            #pragma unroll
            for (int j = 0; j < 8; j++)
                #pragma unroll
                for (int qq = 0; qq < 4; qq++) d[i][j][qq] = 0.0f;

        issue(0, 0);
        issue(1, 1);

        int buf = 0, nbuf = 2;
        for (int it = 0; it < NIT; it++) {
            if (it + 2 < NIT) cp_wait<1>(); else cp_wait<0>();
            __syncthreads();
            if (it + 2 < NIT) issue(it + 2, nbuf);

            const uint32_t sb = sbase + (uint32_t)buf * 16384;
            uint32_t ah[2][4], al[2][4], bb[8][2];
            ldsm4(ah[0], sb + aoff[0]);
            ldsm4(ah[1], sb + aoff[1]);
            ldsm4(al[0], sb + 4096 + aoff[0]);
            ldsm4(al[1], sb + 4096 + aoff[1]);
            #pragma unroll
            for (int p = 0; p < 4; p++) {
                uint32_t r[4];
                ldsm4(r, sb + 8192 + boff[p]);      // W hi
                bb[2 * p][0] = r[0]; bb[2 * p][1] = r[1];
                bb[2 * p + 1][0] = r[2]; bb[2 * p + 1][1] = r[3];
            }
            #pragma unroll
            for (int i = 0; i < 2; i++)
                #pragma unroll
                for (int j = 0; j < 8; j++) {
                    mma16816(d[i][j], ah[i], bb[j]);   // hi*hi
                    mma16816(d[i][j], al[i], bb[j]);   // lo*hi
                }
            #pragma unroll
            for (int p = 0; p < 4; p++) {
                uint32_t r[4];
                ldsm4(r, sb + 12288 + boff[p]);     // W lo
                bb[2 * p][0] = r[0]; bb[2 * p][1] = r[1];
                bb[2 * p + 1][0] = r[2]; bb[2 * p + 1][1] = r[3];
            }
            #pragma unroll
            for (int i = 0; i < 2; i++)
                #pragma unroll
                for (int j = 0; j < 8; j++)
                    mma16816(d[i][j], ah[i], bb[j]);   // hi*lo

            buf  = (buf  == 2) ? 0 : buf + 1;
            nbuf = (nbuf == 2) ? 0 : nbuf + 1;
        }

        // epilogue: bias + tanh -> scatter directly to out[n, idx[n], :]
        float2 bias[8];
        #pragma unroll
        for (int j = 0; j < 8; j++) {
            const int col = block_n + wn * 64 + j * 8 + (lane & 3) * 2;
            bias[j].x = b_in[col] + b_h[col];
            bias[j].y = b_in[col + 1] + b_h[col + 1];
        }
        #pragma unroll
        for (int i = 0; i < 2; i++) {
            const int m0 = block_m + wm * 32 + i * 16 + (lane >> 2);
            const int m1 = m0 + 8;
            const size_t base0 = ((size_t)m0 * LV + (veh_idx[m0] & (LV - 1))) * HD;
            const size_t base1 = ((size_t)m1 * LV + (veh_idx[m1] & (LV - 1))) * HD;
            #pragma unroll
            for (int j = 0; j < 8; j++) {
                const int col = block_n + wn * 64 + j * 8 + (lane & 3) * 2;
                float2 v0, v1;
                v0.x = tanhf(d[i][j][0] + bias[j].x);
                v0.y = tanhf(d[i][j][1] + bias[j].y);
                v1.x = tanhf(d[i][j][2] + bias[j].x);
                v1.y = tanhf(d[i][j][3] + bias[j].y);
                *(float2*)&out[base0 + col] = v0;
                *(float2*)&out[base1 + col] = v1;
            }
        }
    }

    // Copy pool (copy-only CTAs arrive here at t=0; GEMM CTAs after epilogue).
    copy_role((const float4*)memory, (float4*)out, veh_idx, lane);

    // Last CTA out resets all counters for the next graph replay.
    __syncthreads();
    if (tid == 0) {
        const int dcount = atomicAdd(&g_done, 1);
        if (dcount == TOTAL_CTAS - 1) {
            g_copy_ctr = 0;
            #pragma unroll
            for (int i = 0; i < NB / BM; i++) g_xdone[i] = 0;
            #pragma unroll
            for (int i = 0; i < HD / BN; i++) g_wdone[i] = 0;
            __threadfence();
            g_done = 0;
        }
    }
}

extern "C" void kernel_launch(void* const* d_in, const int* in_sizes, int n_in,
                              void* d_out, int out_size)
{
    const float* memory    = (const float*)d_in[0];
    const int*   veh_idx   = (const int*)d_in[1];
    const float* veh_repr  = (const float*)d_in[2];
    const float* cust_repr = (const float*)d_in[3];
    const float* edge_emb  = (const float*)d_in[4];
    const float* W_in      = (const float*)d_in[5];
    const float* b_in      = (const float*)d_in[6];
    const float* W_h       = (const float*)d_in[7];
    const float* b_h       = (const float*)d_in[8];
    float*       out       = (float*)d_out;

    fused_kernel<<<TOTAL_CTAS, 256>>>(memory, veh_idx, veh_repr, cust_repr,
                                      edge_emb, W_in, W_h, b_in, b_h, out);
}